// round 13
// baseline (speedup 1.0000x reference)
#include <cuda_runtime.h>
#include <cuda_fp16.h>
#include <cstdint>

// ---------------------------------------------------------------------------
// QuanvolutionHybrid: closed-form quantum features + conv/bn/residual + fc.
//   Z0 = cos(t4)cos(t0+p0) - sin(t4)sin(t0+p0)sin(p1)
//   Z1 = cos(t0+p0) cos(t1) cos(p1)
//   Z2 = Z1 * cos(p2)
//   Z3 = cos(t3) cos(p2) cos(p3)      (qw[2] provably unused)
// fp16 intermediates; hoisted global loads; FC via HMMA m16n8k16.
// ---------------------------------------------------------------------------

#define MAXB 4096
#define E    784
#define NBIN 32
#define FST  17
#define FIMG (4 * 16 * FST)   // 1088 floats per image tile

typedef unsigned long long u64;

__device__ __half f_h [MAXB * E];
__device__ __half t1_h[MAXB * E];
__device__ __half t2_h[MAXB * E];
__device__ float stats1_g[NBIN * 8];
__device__ float stats2_g[NBIN * 8];

__device__ __forceinline__ u64 fma2(u64 a, u64 b, u64 c) {
    u64 d;
    asm("fma.rn.f32x2 %0, %1, %2, %3;" : "=l"(d) : "l"(a), "l"(b), "l"(c));
    return d;
}
__device__ __forceinline__ u64 pack2(float lo, float hi) {
    u64 d;
    asm("mov.b64 %0, {%1, %2};" : "=l"(d) : "f"(lo), "f"(hi));
    return d;
}
__device__ __forceinline__ float2 unpack2(u64 v) {
    float lo, hi;
    asm("mov.b64 {%0, %1}, %2;" : "=f"(lo), "=f"(hi) : "l"(v));
    return make_float2(lo, hi);
}

union HPack { uint2 u; __half2 h[2]; };

__device__ __forceinline__ void mma_16816(float* d,
    uint32_t a0, uint32_t a1, uint32_t a2, uint32_t a3,
    uint32_t b0, uint32_t b1)
{
    asm volatile(
        "mma.sync.aligned.m16n8k16.row.col.f32.f16.f16.f32 "
        "{%0,%1,%2,%3}, {%4,%5,%6,%7}, {%8,%9}, {%0,%1,%2,%3};"
        : "+f"(d[0]), "+f"(d[1]), "+f"(d[2]), "+f"(d[3])
        : "r"(a0), "r"(a1), "r"(a2), "r"(a3), "r"(b0), "r"(b1));
}

__global__ void k_init() {
    int t = threadIdx.x;
    if (t < NBIN * 8)            stats1_g[t] = 0.f;
    else if (t < 2 * NBIN * 8)   stats2_g[t - NBIN * 8] = 0.f;
}

// wt2: duplicated pairs; u64 index i=(ic*3+kh)*12+kw*4+oc holds (w,w).
__device__ __forceinline__ void stage_weights(const float* __restrict__ w,
                                              float* wt2, int t, int nthr) {
    for (int i = t; i < 144; i += nthr) {
        int oc = i & 3, rest = i >> 2;
        int kw = rest % 3, kh = (rest / 3) % 3, ic = rest / 9;
        float v = w[((oc * 4 + ic) * 3 + kh) * 3 + kw];
        wt2[2 * i] = v;
        wt2[2 * i + 1] = v;
    }
}

// Warp computes 2 output channels (oc=half*2,half*2+1) of the 3x3 conv on one
// image tile. Lane<28: half-row (7 px). Results staged to smem then copied out
// coalesced; stats via warp reduce + binned atomics. Contains __syncthreads.
__device__ __forceinline__ void warp_conv(
    float* myfz, const float* __restrict__ wt2,
    uint2* __restrict__ dst, float* __restrict__ stats,
    int b, int lane, int half, bool act)
{
    u64 acc[2][4];
    #pragma unroll
    for (int o = 0; o < 2; o++)
        #pragma unroll
        for (int p = 0; p < 4; p++) acc[o][p] = 0ull;

    if (act && lane < 28) {
        int row = lane >> 1, w0 = (lane & 1) * 7;
        const ulonglong2* wp2 = reinterpret_cast<const ulonglong2*>(wt2);
        #pragma unroll
        for (int ic = 0; ic < 4; ic++) {
            #pragma unroll
            for (int kh = 0; kh < 3; kh++) {
                const float* rp = myfz + (ic * 16 + row + kh) * FST + w0;
                float a[10];
                #pragma unroll
                for (int q = 0; q < 10; q++) a[q] = rp[q];
                u64 P[9];
                #pragma unroll
                for (int q = 0; q < 9; q++) P[q] = pack2(a[q], a[q + 1]);
                int wbase = (ic * 3 + kh) * 6 + half;
                #pragma unroll
                for (int kw = 0; kw < 3; kw++) {
                    ulonglong2 wv = wp2[wbase + kw * 2];
                    acc[0][0] = fma2(P[kw],     wv.x, acc[0][0]);
                    acc[0][1] = fma2(P[2 + kw], wv.x, acc[0][1]);
                    acc[0][2] = fma2(P[4 + kw], wv.x, acc[0][2]);
                    acc[0][3] = fma2(P[6 + kw], wv.x, acc[0][3]);
                    acc[1][0] = fma2(P[kw],     wv.y, acc[1][0]);
                    acc[1][1] = fma2(P[2 + kw], wv.y, acc[1][1]);
                    acc[1][2] = fma2(P[4 + kw], wv.y, acc[1][2]);
                    acc[1][3] = fma2(P[6 + kw], wv.y, acc[1][3]);
                }
            }
        }
    }
    __syncthreads();                 // tile reads complete block-wide

    float s[4] = {0.f, 0.f, 0.f, 0.f};
    if (act && lane < 28) {
        #pragma unroll
        for (int o = 0; o < 2; o++) {
            int oc = half * 2 + o;
            float2 u0 = unpack2(acc[o][0]);
            float2 u1 = unpack2(acc[o][1]);
            float2 u2 = unpack2(acc[o][2]);
            float2 u3 = unpack2(acc[o][3]);   // .y garbage (px 7)
            float v[7] = {u0.x, u0.y, u1.x, u1.y, u2.x, u2.y, u3.x};
            float* op = myfz + oc * 196 + lane * 7;
            #pragma unroll
            for (int j = 0; j < 7; j++) {
                op[j] = v[j];
                s[o]     += v[j];
                s[2 + o] += v[j] * v[j];
            }
        }
    }
    __syncwarp();
    if (act) {
        const float4* ob4 = reinterpret_cast<const float4*>(myfz);
        #pragma unroll
        for (int it = 0; it < 4; it++) {
            int j = it * 32 + lane;
            if (j < 98) {
                int i = half * 98 + j;
                float4 v = ob4[i];
                HPack pk;
                pk.h[0] = __floats2half2_rn(v.x, v.y);
                pk.h[1] = __floats2half2_rn(v.z, v.w);
                dst[i] = pk.u;
            }
        }
    }
    #pragma unroll
    for (int off = 16; off; off >>= 1)
        #pragma unroll
        for (int c = 0; c < 4; c++)
            s[c] += __shfl_down_sync(0xffffffffu, s[c], off);
    if (act && lane == 0) {
        int base = (b & (NBIN - 1)) * 8 + half * 2;
        atomicAdd(&stats[base],     s[0]);
        atomicAdd(&stats[base + 1], s[1]);
        atomicAdd(&stats[base + 4], s[2]);
        atomicAdd(&stats[base + 5], s[3]);
    }
}

__device__ __forceinline__ void bn_prologue(
    const float* __restrict__ stats, const float* __restrict__ gamma,
    const float* __restrict__ beta, float* sums8, float* sc, float* bi,
    int t, float Ninv)
{
    if (t < 8) {
        float s = 0.f;
        #pragma unroll
        for (int bin = 0; bin < NBIN; bin++) s += stats[bin * 8 + t];
        sums8[t] = s;
    }
    __syncthreads();
    if (t < 4) {
        float mean = sums8[t] * Ninv;
        float var  = sums8[4 + t] * Ninv - mean * mean;
        float s    = gamma[t] * rsqrtf(var + 1e-5f);
        sc[t] = s;
        bi[t] = beta[t] - mean * s;
    }
    __syncthreads();
}

// K1: quantum + conv1 + stats1.  2 warps/image, 2 images per 128-thr block.
__global__ void __launch_bounds__(128) k_quanv_conv1(
    const float* __restrict__ x, const float* __restrict__ qw,
    const float* __restrict__ w1, int B)
{
    __shared__ __align__(16) float fz[2 * FIMG];
    __shared__ __align__(16) float wt2[288];
    int t = threadIdx.x, warp = t >> 5, lane = t & 31;
    int m = warp >> 1, half = warp & 1;
    int b = blockIdx.x * 2 + m;
    bool act = (b < B);

    // --- hoisted x loads ---
    float2 xr0[4], xr1[4];
    const float* xb = x + (size_t)b * E;
    #pragma unroll
    for (int it = 0; it < 4; it++) {
        int j = it * 32 + lane;
        if (act && j < 98) {
            int p = half * 98 + j;
            int i = p / 14, jj = p % 14;
            xr0[it] = *reinterpret_cast<const float2*>(xb + i * 56 + jj * 2);
            xr1[it] = *reinterpret_cast<const float2*>(xb + i * 56 + 28 + jj * 2);
        }
    }

    stage_weights(w1, wt2, t, 128);
    float4* tz = reinterpret_cast<float4*>(fz);
    for (int i = t; i < 2 * FIMG / 4; i += 128)
        tz[i] = make_float4(0.f, 0.f, 0.f, 0.f);
    __syncthreads();

    float* myfz = fz + m * FIMG;
    if (act) {
        float q0 = qw[0], q1 = qw[1], q3 = qw[3], q4 = qw[4];
        float ct1 = __cosf(q1), ct3 = __cosf(q3);
        float st4, ct4; __sincosf(q4, &st4, &ct4);
        uint2* fdst = reinterpret_cast<uint2*>(f_h + (size_t)b * E);
        #pragma unroll
        for (int it = 0; it < 4; it++) {
            int j = it * 32 + lane;
            if (j < 98) {
                int p = half * 98 + j;
                float sa, ca;   __sincosf(q0 + xr0[it].x, &sa, &ca);
                float sp1, cp1; __sincosf(xr0[it].y, &sp1, &cp1);
                float cp2 = __cosf(xr1[it].x), cp3 = __cosf(xr1[it].y);

                float m0 = ct4 * ca - st4 * sa * sp1;
                float m1 = ca * ct1 * cp1;
                float m2 = m1 * cp2;
                float m3 = ct3 * cp2 * cp3;

                HPack pk;
                pk.h[0] = __floats2half2_rn(m0, m1);
                pk.h[1] = __floats2half2_rn(m2, m3);
                fdst[p] = pk.u;

                float mv[4] = {m0, m1, m2, m3};
                #pragma unroll
                for (int q = 0; q < 4; q++) {
                    int e = p * 4 + q, c = e / 196, rr = e % 196;
                    myfz[(c * 16 + rr / 14 + 1) * FST + rr % 14 + 1] = mv[q];
                }
            }
        }
    }
    __syncthreads();
    warp_conv(myfz, wt2, reinterpret_cast<uint2*>(t1_h + (size_t)b * E),
              stats1_g, b, lane, half, act);
}

// K2: bn1+relu + conv2 + stats2.  Same shape; t1 loads hoisted.
__global__ void __launch_bounds__(128) k_conv2(
    const float* __restrict__ w2, const float* __restrict__ g1,
    const float* __restrict__ be1, int B)
{
    __shared__ __align__(16) float fz[2 * FIMG];
    __shared__ __align__(16) float wt2[288];
    __shared__ float sums8[8], sc[4], bi[4];
    int t = threadIdx.x, warp = t >> 5, lane = t & 31;
    int m = warp >> 1, half = warp & 1;
    int b = blockIdx.x * 2 + m;
    bool act = (b < B);

    // --- hoisted t1 loads ---
    uint2 tv[4];
    const uint2* src = reinterpret_cast<const uint2*>(t1_h + (size_t)b * E);
    #pragma unroll
    for (int it = 0; it < 4; it++) {
        int j = it * 32 + lane;
        if (act && j < 98) tv[it] = src[half * 98 + j];
    }

    stage_weights(w2, wt2, t, 128);
    float4* tz = reinterpret_cast<float4*>(fz);
    for (int i = t; i < 2 * FIMG / 4; i += 128)
        tz[i] = make_float4(0.f, 0.f, 0.f, 0.f);

    bn_prologue(stats1_g, g1, be1, sums8, sc, bi, t, 1.f / ((float)B * 196.f));

    float* myfz = fz + m * FIMG;
    if (act) {
        #pragma unroll
        for (int it = 0; it < 4; it++) {
            int j = it * 32 + lane;
            if (j < 98) {
                int e4 = half * 98 + j;
                HPack pk; pk.u = tv[it];
                float2 lo = __half22float2(pk.h[0]);
                float2 hi = __half22float2(pk.h[1]);
                int c = e4 / 49;
                float s = sc[c], o = bi[c];
                float vv[4] = { fmaxf(lo.x*s+o, 0.f), fmaxf(lo.y*s+o, 0.f),
                                fmaxf(hi.x*s+o, 0.f), fmaxf(hi.y*s+o, 0.f) };
                int rr = (e4 * 4) % 196;
                #pragma unroll
                for (int q = 0; q < 4; q++) {
                    int rq = rr + q;
                    myfz[(c * 16 + rq / 14 + 1) * FST + rq % 14 + 1] = vv[q];
                }
            }
        }
    }
    __syncthreads();
    warp_conv(myfz, wt2, reinterpret_cast<uint2*>(t2_h + (size_t)b * E),
              stats2_g, b, lane, half, act);
}

// K3: bn2 + residual + relu + fc + log_softmax via HMMA m16n8k16.
// 64 images per 128-thr block (16/warp); fcw as fp16 smem [16][792];
// activations staged per 112-wide K chunk into fp16 smem [64][120].
#define ACT_ST 120
#define FCW_ST 792

__global__ void __launch_bounds__(128) k_fc(
    const float* __restrict__ g2, const float* __restrict__ be2,
    const float* __restrict__ fcw, const float* __restrict__ fcb,
    float* __restrict__ out, int B)
{
    __shared__ __align__(16) __half fcw_s[16 * FCW_ST];   // 25344 B
    __shared__ __align__(16) __half act_s[64 * ACT_ST];   // 15360 B
    __shared__ float out_s[64][16];                       //  4096 B
    __shared__ float sums8[8], sc[4], bi[4];

    int t = threadIdx.x, warp = t >> 5, lane = t & 31;
    int g = lane >> 2, tg = lane & 3;
    int b0 = blockIdx.x * 64;

    // fcw -> fp16 smem [n][k]; rows 10..15 zeroed (padding logits).
    for (int i = t; i < 7840; i += 128) {
        int n = i / 784, k = i % 784;
        fcw_s[n * FCW_ST + k] = __float2half(fcw[i]);
    }
    for (int i = t; i < 6 * FCW_ST; i += 128)
        fcw_s[10 * FCW_ST + i] = __ushort_as_half(0);

    bn_prologue(stats2_g, g2, be2, sums8, sc, bi, t,
                1.f / ((float)B * 196.f));   // syncs orders fcw_s too

    const uint2* t2u = reinterpret_cast<const uint2*>(t2_h);
    const uint2* fu  = reinterpret_cast<const uint2*>(f_h);

    float d[8];
    #pragma unroll
    for (int k = 0; k < 8; k++) d[k] = 0.f;

    for (int c = 0; c < 7; c++) {
        __syncthreads();    // previous chunk's MMA reads done
        // stage 64 imgs x 112 k of bn2+residual+relu activations (fp16)
        for (int j = t; j < 1792; j += 128) {
            int img = j / 28, k4 = j % 28;
            int bimg = b0 + img;
            uint2 o2 = make_uint2(0u, 0u);
            if (bimg < B) {
                int gi = c * 28 + k4;       // uint2 index within image
                uint2 tvv = t2u[(size_t)bimg * 196 + gi];
                uint2 fvv = fu [(size_t)bimg * 196 + gi];
                int ch = gi / 49;
                float s = sc[ch], o = bi[ch];
                HPack ta; ta.u = tvv;
                HPack fa; fa.u = fvv;
                float2 tl = __half22float2(ta.h[0]), th = __half22float2(ta.h[1]);
                float2 fl = __half22float2(fa.h[0]), fh = __half22float2(fa.h[1]);
                HPack res;
                res.h[0] = __floats2half2_rn(fmaxf(tl.x*s+o+fl.x, 0.f),
                                             fmaxf(tl.y*s+o+fl.y, 0.f));
                res.h[1] = __floats2half2_rn(fmaxf(th.x*s+o+fh.x, 0.f),
                                             fmaxf(th.y*s+o+fh.y, 0.f));
                o2 = res.u;
            }
            *reinterpret_cast<uint2*>(&act_s[img * ACT_ST + k4 * 4]) = o2;
        }
        __syncthreads();
        // 7 MMA k-steps over this chunk
        int rA = (warp * 16 + g) * ACT_ST;
        #pragma unroll
        for (int ks = 0; ks < 7; ks++) {
            int kl = ks * 16 + tg * 2;
            uint32_t a0 = *reinterpret_cast<const uint32_t*>(&act_s[rA + kl]);
            uint32_t a1 = *reinterpret_cast<const uint32_t*>(&act_s[rA + 8 * ACT_ST + kl]);
            uint32_t a2 = *reinterpret_cast<const uint32_t*>(&act_s[rA + kl + 8]);
            uint32_t a3 = *reinterpret_cast<const uint32_t*>(&act_s[rA + 8 * ACT_ST + kl + 8]);
            int kg = c * 112 + ks * 16 + tg * 2;
            uint32_t b0r = *reinterpret_cast<const uint32_t*>(&fcw_s[g * FCW_ST + kg]);
            uint32_t b1r = *reinterpret_cast<const uint32_t*>(&fcw_s[g * FCW_ST + kg + 8]);
            mma_16816(d, a0, a1, a2, a3, b0r, b1r);
            uint32_t b0s = *reinterpret_cast<const uint32_t*>(&fcw_s[(8 + g) * FCW_ST + kg]);
            uint32_t b1s = *reinterpret_cast<const uint32_t*>(&fcw_s[(8 + g) * FCW_ST + kg + 8]);
            mma_16816(d + 4, a0, a1, a2, a3, b0s, b1s);
        }
    }

    // scatter D fragments to out_s [64][16]
    int r0 = warp * 16 + g;
    out_s[r0][tg * 2]         = d[0];
    out_s[r0][tg * 2 + 1]     = d[1];
    out_s[r0 + 8][tg * 2]     = d[2];
    out_s[r0 + 8][tg * 2 + 1] = d[3];
    out_s[r0][8 + tg * 2]         = d[4];
    out_s[r0][8 + tg * 2 + 1]     = d[5];
    out_s[r0 + 8][8 + tg * 2]     = d[6];
    out_s[r0 + 8][8 + tg * 2 + 1] = d[7];
    __syncthreads();

    if (t < 64 && b0 + t < B) {
        float lg[10], mx = -1e30f;
        #pragma unroll
        for (int k = 0; k < 10; k++) {
            lg[k] = out_s[t][k] + fcb[k];
            mx = fmaxf(mx, lg[k]);
        }
        float se = 0.f;
        #pragma unroll
        for (int k = 0; k < 10; k++) se += expf(lg[k] - mx);
        float lse = mx + logf(se);
        #pragma unroll
        for (int k = 0; k < 10; k++)
            out[(size_t)(b0 + t) * 10 + k] = lg[k] - lse;
    }
}

extern "C" void kernel_launch(void* const* d_in, const int* in_sizes, int n_in,
                              void* d_out, int out_size)
{
    const float* x   = (const float*)d_in[0];
    const float* qw  = (const float*)d_in[1];
    const float* w1  = (const float*)d_in[2];
    const float* g1  = (const float*)d_in[3];
    const float* be1 = (const float*)d_in[4];
    const float* w2  = (const float*)d_in[5];
    const float* g2  = (const float*)d_in[6];
    const float* be2 = (const float*)d_in[7];
    const float* fcw = (const float*)d_in[8];
    const float* fcb = (const float*)d_in[9];
    float* out = (float*)d_out;

    int B = in_sizes[0] / E;
    if (B > MAXB) B = MAXB;

    k_init<<<1, 512>>>();
    k_quanv_conv1<<<(B + 1) / 2, 128>>>(x, qw, w1, B);
    k_conv2<<<(B + 1) / 2, 128>>>(w2, g1, be1, B);
    k_fc<<<(B + 63) / 64, 128>>>(g2, be2, fcw, fcb, out, B);
}

// round 14
// speedup vs baseline: 1.5767x; 1.5767x over previous
#include <cuda_runtime.h>
#include <cuda_fp16.h>
#include <cstdint>

// ---------------------------------------------------------------------------
// QuanvolutionHybrid — single persistent kernel, 512 blocks x 256 thr
// (4 blocks/SM guaranteed: regs<=64 via launch_bounds(256,4), 18.6KB smem).
// Perfect balance: 1024 image-groups / 512 blocks = 2 groups each.
// Closed-form circuit (Heisenberg):
//   Z0 = cos(t4)cos(t0+p0) - sin(t4)sin(t0+p0)sin(p1)
//   Z1 = cos(t0+p0) cos(t1) cos(p1)
//   Z2 = Z1 * cos(p2)
//   Z3 = cos(t3) cos(p2) cos(p3)      (qw[2] provably unused)
// f/t1/t2 in global fp16; two atomic grid barriers around BN reductions;
// hoisted global loads in every phase.
// ---------------------------------------------------------------------------

#define MAXB 4096
#define E    784
#define NBIN 32
#define FST  17
#define FIMG (4 * 16 * FST)   // 1088 floats per image tile
#define NBLK 512

typedef unsigned long long u64;

__device__ __half f_h [MAXB * E];
__device__ __half t1_h[MAXB * E];
__device__ __half t2_h[MAXB * E];
__device__ float stats1_g[NBIN * 8];
__device__ float stats2_g[NBIN * 8];
__device__ unsigned sync_ctr;

__device__ __forceinline__ u64 fma2(u64 a, u64 b, u64 c) {
    u64 d;
    asm("fma.rn.f32x2 %0, %1, %2, %3;" : "=l"(d) : "l"(a), "l"(b), "l"(c));
    return d;
}
__device__ __forceinline__ u64 pack2(float lo, float hi) {
    u64 d;
    asm("mov.b64 %0, {%1, %2};" : "=l"(d) : "f"(lo), "f"(hi));
    return d;
}
__device__ __forceinline__ float2 unpack2(u64 v) {
    float lo, hi;
    asm("mov.b64 {%0, %1}, %2;" : "=f"(lo), "=f"(hi) : "l"(v));
    return make_float2(lo, hi);
}

union HPack { uint2 u; __half2 h[2]; };

__global__ void k_init() {
    int t = threadIdx.x;
    if (t == 0) sync_ctr = 0u;
    if (t < NBIN * 8)            stats1_g[t] = 0.f;
    else if (t < 2 * NBIN * 8)   stats2_g[t - NBIN * 8] = 0.f;
}

// Release-acquire grid barrier (all NBLK blocks co-resident by construction:
// 512 <= 4/SM * 148 SMs; 4/SM guaranteed by regs<=64 and 74.5KB total smem).
__device__ __forceinline__ void grid_sync(unsigned target) {
    __syncthreads();
    if (threadIdx.x == 0) {
        __threadfence();
        atomicAdd(&sync_ctr, 1u);
        while (*((volatile unsigned*)&sync_ctr) < target) __nanosleep(64);
        __threadfence();
    }
    __syncthreads();
}

// wt2: duplicated weight pairs; u64 index i=(ic*3+kh)*12+kw*4+oc holds (w,w).
__device__ __forceinline__ void stage_weights(const float* __restrict__ w,
                                              float* wt2, int t) {
    if (t < 144) {
        int oc = t & 3, rest = t >> 2;
        int kw = rest % 3, kh = (rest / 3) % 3, ic = rest / 9;
        float v = w[((oc * 4 + ic) * 3 + kh) * 3 + kw];
        wt2[2 * t] = v;
        wt2[2 * t + 1] = v;
    }
}

// Warp computes 2 output channels (oc=half*2, half*2+1).  Lane<28: half-row
// (7 px).  After block sync, results staged to smem (tile dead) and copied
// to global as coalesced uint2 halves; per-channel stats -> binned atomics.
// Contains __syncthreads: must be called by ALL threads of the block.
__device__ __forceinline__ void warp_conv(
    float* myfz, const float* __restrict__ wt2,
    uint2* __restrict__ dst, float* __restrict__ stats,
    int b, int lane, int half, bool act)
{
    u64 acc[2][4];
    #pragma unroll
    for (int o = 0; o < 2; o++)
        #pragma unroll
        for (int p = 0; p < 4; p++) acc[o][p] = 0ull;

    if (act && lane < 28) {
        int row = lane >> 1, w0 = (lane & 1) * 7;
        const ulonglong2* wp2 = reinterpret_cast<const ulonglong2*>(wt2);
        #pragma unroll
        for (int ic = 0; ic < 4; ic++) {
            #pragma unroll
            for (int kh = 0; kh < 3; kh++) {
                const float* rp = myfz + (ic * 16 + row + kh) * FST + w0;
                float a[10];
                #pragma unroll
                for (int q = 0; q < 10; q++) a[q] = rp[q];
                u64 P[9];
                #pragma unroll
                for (int q = 0; q < 9; q++) P[q] = pack2(a[q], a[q + 1]);
                int wbase = (ic * 3 + kh) * 6 + half;
                #pragma unroll
                for (int kw = 0; kw < 3; kw++) {
                    ulonglong2 wv = wp2[wbase + kw * 2];
                    acc[0][0] = fma2(P[kw],     wv.x, acc[0][0]);
                    acc[0][1] = fma2(P[2 + kw], wv.x, acc[0][1]);
                    acc[0][2] = fma2(P[4 + kw], wv.x, acc[0][2]);
                    acc[0][3] = fma2(P[6 + kw], wv.x, acc[0][3]);
                    acc[1][0] = fma2(P[kw],     wv.y, acc[1][0]);
                    acc[1][1] = fma2(P[2 + kw], wv.y, acc[1][1]);
                    acc[1][2] = fma2(P[4 + kw], wv.y, acc[1][2]);
                    acc[1][3] = fma2(P[6 + kw], wv.y, acc[1][3]);
                }
            }
        }
    }
    __syncthreads();                    // tile reads complete block-wide

    float s[4] = {0.f, 0.f, 0.f, 0.f};
    if (act && lane < 28) {
        #pragma unroll
        for (int o = 0; o < 2; o++) {
            int oc = half * 2 + o;
            float2 u0 = unpack2(acc[o][0]);
            float2 u1 = unpack2(acc[o][1]);
            float2 u2 = unpack2(acc[o][2]);
            float2 u3 = unpack2(acc[o][3]);   // .y garbage (px 7)
            float v[7] = {u0.x, u0.y, u1.x, u1.y, u2.x, u2.y, u3.x};
            float* op = myfz + oc * 196 + lane * 7;
            #pragma unroll
            for (int j = 0; j < 7; j++) {
                op[j] = v[j];
                s[o]     += v[j];
                s[2 + o] += v[j] * v[j];
            }
        }
    }
    __syncwarp();
    if (act) {
        const float4* ob4 = reinterpret_cast<const float4*>(myfz);
        #pragma unroll
        for (int it = 0; it < 4; it++) {
            int j = it * 32 + lane;
            if (j < 98) {
                int i = half * 98 + j;
                float4 v = ob4[i];
                HPack pk;
                pk.h[0] = __floats2half2_rn(v.x, v.y);
                pk.h[1] = __floats2half2_rn(v.z, v.w);
                dst[i] = pk.u;
            }
        }
    }
    #pragma unroll
    for (int off = 16; off; off >>= 1)
        #pragma unroll
        for (int c = 0; c < 4; c++)
            s[c] += __shfl_down_sync(0xffffffffu, s[c], off);
    if (act && lane == 0) {
        int base = (b & (NBIN - 1)) * 8 + half * 2;
        atomicAdd(&stats[base],     s[0]);
        atomicAdd(&stats[base + 1], s[1]);
        atomicAdd(&stats[base + 4], s[2]);
        atomicAdd(&stats[base + 5], s[3]);
    }
}

__device__ __forceinline__ void bn_prologue(
    const float* __restrict__ stats, const float* __restrict__ gamma,
    const float* __restrict__ beta, float* sums8, float* sc, float* bi,
    int t, float Ninv)
{
    if (t < 8) {
        float s = 0.f;
        #pragma unroll
        for (int bin = 0; bin < NBIN; bin++) s += stats[bin * 8 + t];
        sums8[t] = s;
    }
    __syncthreads();
    if (t < 4) {
        float mean = sums8[t] * Ninv;
        float var  = sums8[4 + t] * Ninv - mean * mean;
        float s    = gamma[t] * rsqrtf(var + 1e-5f);
        sc[t] = s;
        bi[t] = beta[t] - mean * s;
    }
    __syncthreads();
}

__global__ void __launch_bounds__(256, 4) k_fused(
    const float* __restrict__ x, const float* __restrict__ qw,
    const float* __restrict__ w1, const float* __restrict__ g1,
    const float* __restrict__ be1, const float* __restrict__ w2,
    const float* __restrict__ g2, const float* __restrict__ be2,
    const float* __restrict__ fcw, const float* __restrict__ fcb,
    float* __restrict__ out, int B)
{
    __shared__ __align__(16) float tile[4 * FIMG];   // 17408 B (4 tile slots)
    __shared__ __align__(16) float wt2[288];
    __shared__ float sums8[8], sc[4], bi[4];

    int t = threadIdx.x, warp = t >> 5, lane = t & 31;
    int m = warp >> 1, half = warp & 1;     // tile slot (0..3), oc-half
    float Ninv = 1.f / ((float)B * 196.f);

    // ======================= PHASE 1: quantum + conv1 =======================
    stage_weights(w1, wt2, t);

    float q0 = qw[0], q1 = qw[1], q3 = qw[3], q4 = qw[4];
    float ct1 = __cosf(q1), ct3 = __cosf(q3);
    float st4, ct4; __sincosf(q4, &st4, &ct4);

    #pragma unroll
    for (int gi = 0; gi < 2; gi++) {
        int g = blockIdx.x + gi * NBLK;      // 1024 groups, 2 per block
        int b = g * 4 + m;
        bool act = (b < B);

        // hoisted x loads (overlap tile zeroing)
        float2 xr0[4], xr1[4];
        const float* xb = x + (size_t)b * E;
        #pragma unroll
        for (int it = 0; it < 4; it++) {
            int j = it * 32 + lane;
            if (act && j < 98) {
                int p = half * 98 + j;
                int i = p / 14, jj = p % 14;
                xr0[it] = *reinterpret_cast<const float2*>(xb + i * 56 + jj * 2);
                xr1[it] = *reinterpret_cast<const float2*>(xb + i * 56 + 28 + jj * 2);
            }
        }

        __syncthreads();                 // previous iteration's tile dead
        float4* tz = reinterpret_cast<float4*>(tile);
        #pragma unroll
        for (int k = 0; k < 5; k++) {
            int i = t + 256 * k;
            if (i < FIMG) tz[i] = make_float4(0.f, 0.f, 0.f, 0.f);
        }
        __syncthreads();

        float* myfz = tile + m * FIMG;
        if (act) {
            uint2* fdst = reinterpret_cast<uint2*>(f_h + (size_t)b * E);
            #pragma unroll
            for (int it = 0; it < 4; it++) {
                int j = it * 32 + lane;
                if (j < 98) {
                    int p = half * 98 + j;
                    float sa, ca;   __sincosf(q0 + xr0[it].x, &sa, &ca);
                    float sp1, cp1; __sincosf(xr0[it].y, &sp1, &cp1);
                    float cp2 = __cosf(xr1[it].x), cp3 = __cosf(xr1[it].y);

                    float m0 = ct4 * ca - st4 * sa * sp1;
                    float m1 = ca * ct1 * cp1;
                    float m2 = m1 * cp2;
                    float m3 = ct3 * cp2 * cp3;

                    HPack pk;
                    pk.h[0] = __floats2half2_rn(m0, m1);
                    pk.h[1] = __floats2half2_rn(m2, m3);
                    fdst[p] = pk.u;

                    float mv[4] = {m0, m1, m2, m3};
                    #pragma unroll
                    for (int q = 0; q < 4; q++) {
                        int e = p * 4 + q, c = e / 196, rr = e % 196;
                        myfz[(c * 16 + rr / 14 + 1) * FST + rr % 14 + 1] = mv[q];
                    }
                }
            }
        }
        __syncthreads();
        warp_conv(myfz, wt2,
                  reinterpret_cast<uint2*>(t1_h + (size_t)b * E),
                  stats1_g, b, lane, half, act);
    }

    grid_sync(NBLK);                     // stats1 complete everywhere

    // ======================= PHASE 2: bn1+relu + conv2 ======================
    stage_weights(w2, wt2, t);
    bn_prologue(stats1_g, g1, be1, sums8, sc, bi, t, Ninv);

    #pragma unroll
    for (int gi = 0; gi < 2; gi++) {
        int g = blockIdx.x + gi * NBLK;
        int b = g * 4 + m;
        bool act = (b < B);

        // hoisted t1 loads
        uint2 tv[4];
        const uint2* src = reinterpret_cast<const uint2*>(t1_h + (size_t)b * E);
        #pragma unroll
        for (int it = 0; it < 4; it++) {
            int j = it * 32 + lane;
            if (act && j < 98) tv[it] = src[half * 98 + j];
        }

        __syncthreads();
        float4* tz = reinterpret_cast<float4*>(tile);
        #pragma unroll
        for (int k = 0; k < 5; k++) {
            int i = t + 256 * k;
            if (i < FIMG) tz[i] = make_float4(0.f, 0.f, 0.f, 0.f);
        }
        __syncthreads();

        float* myfz = tile + m * FIMG;
        if (act) {
            #pragma unroll
            for (int it = 0; it < 4; it++) {
                int j = it * 32 + lane;
                if (j < 98) {
                    int e4 = half * 98 + j;
                    HPack pk; pk.u = tv[it];
                    float2 lo = __half22float2(pk.h[0]);
                    float2 hi = __half22float2(pk.h[1]);
                    int c = e4 / 49;
                    float s = sc[c], o = bi[c];
                    float vv[4] = { fmaxf(lo.x*s+o, 0.f), fmaxf(lo.y*s+o, 0.f),
                                    fmaxf(hi.x*s+o, 0.f), fmaxf(hi.y*s+o, 0.f) };
                    int rr = (e4 * 4) % 196;
                    #pragma unroll
                    for (int q = 0; q < 4; q++) {
                        int rq = rr + q;
                        myfz[(c * 16 + rq / 14 + 1) * FST + rq % 14 + 1] = vv[q];
                    }
                }
            }
        }
        __syncthreads();
        warp_conv(myfz, wt2,
                  reinterpret_cast<uint2*>(t2_h + (size_t)b * E),
                  stats2_g, b, lane, half, act);
    }

    grid_sync(2 * NBLK);                 // stats2 complete everywhere

    // ============ PHASE 3: bn2 + residual + relu + fc + softmax =============
    int b3 = blockIdx.x * 8 + warp;      // 1 image per warp, 8 per block
    bool act3 = (b3 < B);

    // hoisted t2/f loads ahead of bn_prologue
    uint2 tv[7], fv[7];
    const uint2* tA = reinterpret_cast<const uint2*>(t2_h + (size_t)b3 * E);
    const uint2* fA = reinterpret_cast<const uint2*>(f_h  + (size_t)b3 * E);
    #pragma unroll
    for (int it = 0; it < 7; it++) {
        int i = it * 32 + lane;
        if (act3 && i < 196) { tv[it] = tA[i]; fv[it] = fA[i]; }
    }

    bn_prologue(stats2_g, g2, be2, sums8, sc, bi, t, Ninv);
    if (!act3) return;

    const float4* fw4 = reinterpret_cast<const float4*>(fcw);
    u64 acc[10];
    #pragma unroll
    for (int k = 0; k < 10; k++) acc[k] = 0ull;

    #pragma unroll
    for (int it = 0; it < 7; it++) {
        int i = it * 32 + lane;
        if (i < 196) {
            int c = i / 49;
            float s = sc[c], o = bi[c];
            HPack ta; ta.u = tv[it];
            HPack fa; fa.u = fv[it];
            float2 tl = __half22float2(ta.h[0]), th = __half22float2(ta.h[1]);
            float2 fl = __half22float2(fa.h[0]), fh = __half22float2(fa.h[1]);
            u64 A1 = pack2(fmaxf(tl.x*s+o+fl.x, 0.f), fmaxf(tl.y*s+o+fl.y, 0.f));
            u64 A2 = pack2(fmaxf(th.x*s+o+fh.x, 0.f), fmaxf(th.y*s+o+fh.y, 0.f));
            #pragma unroll
            for (int k = 0; k < 10; k++) {
                float4 wv = __ldg(&fw4[k * 196 + i]);
                acc[k] = fma2(A1, pack2(wv.x, wv.y), acc[k]);
                acc[k] = fma2(A2, pack2(wv.z, wv.w), acc[k]);
            }
        }
    }
    float sA[10];
    #pragma unroll
    for (int k = 0; k < 10; k++) {
        float2 u = unpack2(acc[k]);
        sA[k] = u.x + u.y;
    }
    #pragma unroll
    for (int off = 16; off; off >>= 1)
        #pragma unroll
        for (int k = 0; k < 10; k++)
            sA[k] += __shfl_down_sync(0xffffffffu, sA[k], off);

    if (lane == 0) {
        float lg[10], mx = -1e30f;
        #pragma unroll
        for (int k = 0; k < 10; k++) {
            lg[k] = sA[k] + fcb[k];
            mx = fmaxf(mx, lg[k]);
        }
        float se = 0.f;
        #pragma unroll
        for (int k = 0; k < 10; k++) se += expf(lg[k] - mx);
        float lse = mx + logf(se);
        #pragma unroll
        for (int k = 0; k < 10; k++)
            out[(size_t)b3 * 10 + k] = lg[k] - lse;
    }
}

extern "C" void kernel_launch(void* const* d_in, const int* in_sizes, int n_in,
                              void* d_out, int out_size)
{
    const float* x   = (const float*)d_in[0];
    const float* qw  = (const float*)d_in[1];
    const float* w1  = (const float*)d_in[2];
    const float* g1  = (const float*)d_in[3];
    const float* be1 = (const float*)d_in[4];
    const float* w2  = (const float*)d_in[5];
    const float* g2  = (const float*)d_in[6];
    const float* be2 = (const float*)d_in[7];
    const float* fcw = (const float*)d_in[8];
    const float* fcb = (const float*)d_in[9];
    float* out = (float*)d_out;

    int B = in_sizes[0] / E;
    if (B > MAXB) B = MAXB;

    k_init<<<1, 512>>>();
    k_fused<<<NBLK, 256>>>(x, qw, w1, g1, be1, w2, g2, be2, fcw, fcb, out, B);
}

// round 15
// speedup vs baseline: 1.8489x; 1.1726x over previous
#include <cuda_runtime.h>
#include <cuda_fp16.h>
#include <cstdint>

// ---------------------------------------------------------------------------
// QuanvolutionHybrid: closed-form quantum features + conv/bn/residual + fc.
//   Z0 = cos(t4)cos(t0+p0) - sin(t4)sin(t0+p0)sin(p1)
//   Z1 = cos(t0+p0) cos(t1) cos(p1)
//   Z2 = Z1 * cos(p2)
//   Z3 = cos(t3) cos(p2) cos(p3)      (qw[2] provably unused)
// fp16 intermediates; hoisted global loads; stats zeroing folded into the
// pipeline (k1 zeroes stats2, k_fc zeroes stats1) -> no k_init launch.
// k_fc: 2 images per warp share each fcw load.
// ---------------------------------------------------------------------------

#define MAXB 4096
#define E    784
#define NBIN 32
#define FST  17
#define FIMG (4 * 16 * FST)   // 1088 floats per image tile

typedef unsigned long long u64;

__device__ __half f_h [MAXB * E];
__device__ __half t1_h[MAXB * E];
__device__ __half t2_h[MAXB * E];
__device__ float stats1_g[NBIN * 8];   // zero at load; k_fc re-zeroes each run
__device__ float stats2_g[NBIN * 8];   // zero at load; k1  re-zeroes each run

__device__ __forceinline__ u64 fma2(u64 a, u64 b, u64 c) {
    u64 d;
    asm("fma.rn.f32x2 %0, %1, %2, %3;" : "=l"(d) : "l"(a), "l"(b), "l"(c));
    return d;
}
__device__ __forceinline__ u64 pack2(float lo, float hi) {
    u64 d;
    asm("mov.b64 %0, {%1, %2};" : "=l"(d) : "f"(lo), "f"(hi));
    return d;
}
__device__ __forceinline__ float2 unpack2(u64 v) {
    float lo, hi;
    asm("mov.b64 {%0, %1}, %2;" : "=f"(lo), "=f"(hi) : "l"(v));
    return make_float2(lo, hi);
}

union HPack { uint2 u; __half2 h[2]; };

// wt2: duplicated pairs; u64 index i=(ic*3+kh)*12+kw*4+oc holds (w,w).
__device__ __forceinline__ void stage_weights(const float* __restrict__ w,
                                              float* wt2, int t, int nthr) {
    for (int i = t; i < 144; i += nthr) {
        int oc = i & 3, rest = i >> 2;
        int kw = rest % 3, kh = (rest / 3) % 3, ic = rest / 9;
        float v = w[((oc * 4 + ic) * 3 + kh) * 3 + kw];
        wt2[2 * i] = v;
        wt2[2 * i + 1] = v;
    }
}

// Warp computes 2 output channels (oc=half*2,half*2+1) of the 3x3 conv on one
// image tile. Lane<28: half-row (7 px). Results staged to smem (tile dead
// after block sync) then copied out coalesced; stats via warp reduce+atomics.
// Contains __syncthreads: call from ALL threads of the block.
__device__ __forceinline__ void warp_conv(
    float* myfz, const float* __restrict__ wt2,
    uint2* __restrict__ dst, float* __restrict__ stats,
    int b, int lane, int half, bool act)
{
    u64 acc[2][4];
    #pragma unroll
    for (int o = 0; o < 2; o++)
        #pragma unroll
        for (int p = 0; p < 4; p++) acc[o][p] = 0ull;

    if (act && lane < 28) {
        int row = lane >> 1, w0 = (lane & 1) * 7;
        const ulonglong2* wp2 = reinterpret_cast<const ulonglong2*>(wt2);
        #pragma unroll
        for (int ic = 0; ic < 4; ic++) {
            #pragma unroll
            for (int kh = 0; kh < 3; kh++) {
                const float* rp = myfz + (ic * 16 + row + kh) * FST + w0;
                float a[10];
                #pragma unroll
                for (int q = 0; q < 10; q++) a[q] = rp[q];
                u64 P[9];
                #pragma unroll
                for (int q = 0; q < 9; q++) P[q] = pack2(a[q], a[q + 1]);
                int wbase = (ic * 3 + kh) * 6 + half;
                #pragma unroll
                for (int kw = 0; kw < 3; kw++) {
                    ulonglong2 wv = wp2[wbase + kw * 2];
                    acc[0][0] = fma2(P[kw],     wv.x, acc[0][0]);
                    acc[0][1] = fma2(P[2 + kw], wv.x, acc[0][1]);
                    acc[0][2] = fma2(P[4 + kw], wv.x, acc[0][2]);
                    acc[0][3] = fma2(P[6 + kw], wv.x, acc[0][3]);
                    acc[1][0] = fma2(P[kw],     wv.y, acc[1][0]);
                    acc[1][1] = fma2(P[2 + kw], wv.y, acc[1][1]);
                    acc[1][2] = fma2(P[4 + kw], wv.y, acc[1][2]);
                    acc[1][3] = fma2(P[6 + kw], wv.y, acc[1][3]);
                }
            }
        }
    }
    __syncthreads();                 // tile reads complete block-wide

    float s[4] = {0.f, 0.f, 0.f, 0.f};
    if (act && lane < 28) {
        #pragma unroll
        for (int o = 0; o < 2; o++) {
            int oc = half * 2 + o;
            float2 u0 = unpack2(acc[o][0]);
            float2 u1 = unpack2(acc[o][1]);
            float2 u2 = unpack2(acc[o][2]);
            float2 u3 = unpack2(acc[o][3]);   // .y garbage (px 7)
            float v[7] = {u0.x, u0.y, u1.x, u1.y, u2.x, u2.y, u3.x};
            float* op = myfz + oc * 196 + lane * 7;
            #pragma unroll
            for (int j = 0; j < 7; j++) {
                op[j] = v[j];
                s[o]     += v[j];
                s[2 + o] += v[j] * v[j];
            }
        }
    }
    __syncwarp();
    if (act) {
        const float4* ob4 = reinterpret_cast<const float4*>(myfz);
        #pragma unroll
        for (int it = 0; it < 4; it++) {
            int j = it * 32 + lane;
            if (j < 98) {
                int i = half * 98 + j;
                float4 v = ob4[i];
                HPack pk;
                pk.h[0] = __floats2half2_rn(v.x, v.y);
                pk.h[1] = __floats2half2_rn(v.z, v.w);
                dst[i] = pk.u;
            }
        }
    }
    #pragma unroll
    for (int off = 16; off; off >>= 1)
        #pragma unroll
        for (int c = 0; c < 4; c++)
            s[c] += __shfl_down_sync(0xffffffffu, s[c], off);
    if (act && lane == 0) {
        int base = (b & (NBIN - 1)) * 8 + half * 2;
        atomicAdd(&stats[base],     s[0]);
        atomicAdd(&stats[base + 1], s[1]);
        atomicAdd(&stats[base + 4], s[2]);
        atomicAdd(&stats[base + 5], s[3]);
    }
}

__device__ __forceinline__ void bn_prologue(
    const float* __restrict__ stats, const float* __restrict__ gamma,
    const float* __restrict__ beta, float* sums8, float* sc, float* bi,
    int t, float Ninv)
{
    if (t < 8) {
        float s = 0.f;
        #pragma unroll
        for (int bin = 0; bin < NBIN; bin++) s += stats[bin * 8 + t];
        sums8[t] = s;
    }
    __syncthreads();
    if (t < 4) {
        float mean = sums8[t] * Ninv;
        float var  = sums8[4 + t] * Ninv - mean * mean;
        float s    = gamma[t] * rsqrtf(var + 1e-5f);
        sc[t] = s;
        bi[t] = beta[t] - mean * s;
    }
    __syncthreads();
}

// K1: quantum + conv1 + stats1.  2 warps/image, 2 images per 128-thr block.
// Block 0 also zeroes stats2 for this run (nothing reads stats2 during k1).
__global__ void __launch_bounds__(128) k_quanv_conv1(
    const float* __restrict__ x, const float* __restrict__ qw,
    const float* __restrict__ w1, int B)
{
    __shared__ __align__(16) float fz[2 * FIMG];
    __shared__ __align__(16) float wt2[288];
    int t = threadIdx.x, warp = t >> 5, lane = t & 31;
    int m = warp >> 1, half = warp & 1;
    int b = blockIdx.x * 2 + m;
    bool act = (b < B);

    if (blockIdx.x == 0) {           // fold k_init: zero stats2
        stats2_g[t] = 0.f;
        stats2_g[t + 128] = 0.f;
    }

    // --- hoisted x loads (4 px per lane max) ---
    float2 xr0[4], xr1[4];
    const float* xb = x + (size_t)b * E;
    #pragma unroll
    for (int it = 0; it < 4; it++) {
        int j = it * 32 + lane;
        if (act && j < 98) {
            int p = half * 98 + j;
            int i = p / 14, jj = p % 14;
            xr0[it] = *reinterpret_cast<const float2*>(xb + i * 56 + jj * 2);
            xr1[it] = *reinterpret_cast<const float2*>(xb + i * 56 + 28 + jj * 2);
        }
    }

    stage_weights(w1, wt2, t, 128);
    float4* tz = reinterpret_cast<float4*>(fz);
    for (int i = t; i < 2 * FIMG / 4; i += 128)
        tz[i] = make_float4(0.f, 0.f, 0.f, 0.f);
    __syncthreads();

    float* myfz = fz + m * FIMG;
    if (act) {
        float q0 = qw[0], q1 = qw[1], q3 = qw[3], q4 = qw[4];
        float ct1 = __cosf(q1), ct3 = __cosf(q3);
        float st4, ct4; __sincosf(q4, &st4, &ct4);
        uint2* fdst = reinterpret_cast<uint2*>(f_h + (size_t)b * E);
        #pragma unroll
        for (int it = 0; it < 4; it++) {
            int j = it * 32 + lane;
            if (j < 98) {
                int p = half * 98 + j;
                float sa, ca;   __sincosf(q0 + xr0[it].x, &sa, &ca);
                float sp1, cp1; __sincosf(xr0[it].y, &sp1, &cp1);
                float cp2 = __cosf(xr1[it].x), cp3 = __cosf(xr1[it].y);

                float m0 = ct4 * ca - st4 * sa * sp1;
                float m1 = ca * ct1 * cp1;
                float m2 = m1 * cp2;
                float m3 = ct3 * cp2 * cp3;

                HPack pk;
                pk.h[0] = __floats2half2_rn(m0, m1);
                pk.h[1] = __floats2half2_rn(m2, m3);
                fdst[p] = pk.u;

                float mv[4] = {m0, m1, m2, m3};
                #pragma unroll
                for (int q = 0; q < 4; q++) {
                    int e = p * 4 + q, c = e / 196, rr = e % 196;
                    myfz[(c * 16 + rr / 14 + 1) * FST + rr % 14 + 1] = mv[q];
                }
            }
        }
    }
    __syncthreads();
    warp_conv(myfz, wt2, reinterpret_cast<uint2*>(t1_h + (size_t)b * E),
              stats1_g, b, lane, half, act);
}

// K2: bn1+relu + conv2 + stats2.  Same shape; t1 loads hoisted ahead of
// zeroing + bn_prologue.
__global__ void __launch_bounds__(128) k_conv2(
    const float* __restrict__ w2, const float* __restrict__ g1,
    const float* __restrict__ be1, int B)
{
    __shared__ __align__(16) float fz[2 * FIMG];
    __shared__ __align__(16) float wt2[288];
    __shared__ float sums8[8], sc[4], bi[4];
    int t = threadIdx.x, warp = t >> 5, lane = t & 31;
    int m = warp >> 1, half = warp & 1;
    int b = blockIdx.x * 2 + m;
    bool act = (b < B);

    // --- hoisted t1 loads ---
    uint2 tv[4];
    const uint2* src = reinterpret_cast<const uint2*>(t1_h + (size_t)b * E);
    #pragma unroll
    for (int it = 0; it < 4; it++) {
        int j = it * 32 + lane;
        if (act && j < 98) tv[it] = src[half * 98 + j];
    }

    stage_weights(w2, wt2, t, 128);
    float4* tz = reinterpret_cast<float4*>(fz);
    for (int i = t; i < 2 * FIMG / 4; i += 128)
        tz[i] = make_float4(0.f, 0.f, 0.f, 0.f);

    bn_prologue(stats1_g, g1, be1, sums8, sc, bi, t, 1.f / ((float)B * 196.f));

    float* myfz = fz + m * FIMG;
    if (act) {
        #pragma unroll
        for (int it = 0; it < 4; it++) {
            int j = it * 32 + lane;
            if (j < 98) {
                int e4 = half * 98 + j;
                HPack pk; pk.u = tv[it];
                float2 lo = __half22float2(pk.h[0]);
                float2 hi = __half22float2(pk.h[1]);
                int c = e4 / 49;
                float s = sc[c], o = bi[c];
                float vv[4] = { fmaxf(lo.x*s+o, 0.f), fmaxf(lo.y*s+o, 0.f),
                                fmaxf(hi.x*s+o, 0.f), fmaxf(hi.y*s+o, 0.f) };
                int rr = (e4 * 4) % 196;
                #pragma unroll
                for (int q = 0; q < 4; q++) {
                    int rq = rr + q;
                    myfz[(c * 16 + rq / 14 + 1) * FST + rq % 14 + 1] = vv[q];
                }
            }
        }
    }
    __syncthreads();
    warp_conv(myfz, wt2, reinterpret_cast<uint2*>(t2_h + (size_t)b * E),
              stats2_g, b, lane, half, act);
}

// K3: bn2 + residual + relu + fc + log_softmax.  2 images per warp (each fcw
// load feeds both), 8 images per 128-thr block.  Image A's t2/f hoisted;
// image B loaded inline.  Block 0 zeroes stats1 for the next run.
__global__ void __launch_bounds__(128) k_fc(
    const float* __restrict__ g2, const float* __restrict__ be2,
    const float* __restrict__ fcw, const float* __restrict__ fcb,
    float* __restrict__ out, int B)
{
    __shared__ float sums8[8], sc[4], bi[4];
    int t = threadIdx.x, warp = t >> 5, lane = t & 31;
    int b0 = blockIdx.x * 8 + warp * 2;
    bool a0 = (b0 < B), a1 = (b0 + 1 < B);
    int c0 = a0 ? b0 : 0, c1 = a1 ? b0 + 1 : c0;

    if (blockIdx.x == 0) {           // fold k_init: zero stats1 (dead here)
        stats1_g[t] = 0.f;
        stats1_g[t + 128] = 0.f;
    }

    // --- hoisted image-A loads (7 uint2 each) ---
    uint2 tvA[7], fvA[7];
    const uint2* tA = reinterpret_cast<const uint2*>(t2_h + (size_t)c0 * E);
    const uint2* fA = reinterpret_cast<const uint2*>(f_h  + (size_t)c0 * E);
    #pragma unroll
    for (int it = 0; it < 7; it++) {
        int i = it * 32 + lane;
        if (a0 && i < 196) { tvA[it] = tA[i]; fvA[it] = fA[i]; }
    }

    bn_prologue(stats2_g, g2, be2, sums8, sc, bi, t, 1.f / ((float)B * 196.f));
    if (!a0) return;

    const uint2* tB = reinterpret_cast<const uint2*>(t2_h + (size_t)c1 * E);
    const uint2* fB = reinterpret_cast<const uint2*>(f_h  + (size_t)c1 * E);
    const float4* fw4 = reinterpret_cast<const float4*>(fcw);

    u64 accA[10], accB[10];
    #pragma unroll
    for (int k = 0; k < 10; k++) { accA[k] = 0ull; accB[k] = 0ull; }

    #pragma unroll
    for (int it = 0; it < 7; it++) {
        int i = it * 32 + lane;
        if (i < 196) {
            int c = i / 49;
            float s = sc[c], o = bi[c];

            HPack ta; ta.u = tvA[it];
            HPack fa; fa.u = fvA[it];
            float2 tl = __half22float2(ta.h[0]), th = __half22float2(ta.h[1]);
            float2 fl = __half22float2(fa.h[0]), fh = __half22float2(fa.h[1]);
            u64 A1 = pack2(fmaxf(tl.x*s+o+fl.x, 0.f), fmaxf(tl.y*s+o+fl.y, 0.f));
            u64 A2 = pack2(fmaxf(th.x*s+o+fh.x, 0.f), fmaxf(th.y*s+o+fh.y, 0.f));

            HPack tb; tb.u = tB[i];
            HPack fb; fb.u = fB[i];
            float2 ul = __half22float2(tb.h[0]), uh = __half22float2(tb.h[1]);
            float2 gl = __half22float2(fb.h[0]), gh = __half22float2(fb.h[1]);
            u64 B1 = pack2(fmaxf(ul.x*s+o+gl.x, 0.f), fmaxf(ul.y*s+o+gl.y, 0.f));
            u64 B2 = pack2(fmaxf(uh.x*s+o+gh.x, 0.f), fmaxf(uh.y*s+o+gh.y, 0.f));

            #pragma unroll
            for (int k = 0; k < 10; k++) {
                float4 wv = __ldg(&fw4[k * 196 + i]);
                u64 w1p = pack2(wv.x, wv.y), w2p = pack2(wv.z, wv.w);
                accA[k] = fma2(A1, w1p, accA[k]);
                accA[k] = fma2(A2, w2p, accA[k]);
                accB[k] = fma2(B1, w1p, accB[k]);
                accB[k] = fma2(B2, w2p, accB[k]);
            }
        }
    }
    float sA[10], sB[10];
    #pragma unroll
    for (int k = 0; k < 10; k++) {
        float2 ua = unpack2(accA[k]); sA[k] = ua.x + ua.y;
        float2 ub = unpack2(accB[k]); sB[k] = ub.x + ub.y;
    }
    #pragma unroll
    for (int off = 16; off; off >>= 1)
        #pragma unroll
        for (int k = 0; k < 10; k++) {
            sA[k] += __shfl_down_sync(0xffffffffu, sA[k], off);
            sB[k] += __shfl_down_sync(0xffffffffu, sB[k], off);
        }

    if (lane == 0) {
        float lg[10], mx = -1e30f;
        #pragma unroll
        for (int k = 0; k < 10; k++) {
            lg[k] = sA[k] + fcb[k];
            mx = fmaxf(mx, lg[k]);
        }
        float se = 0.f;
        #pragma unroll
        for (int k = 0; k < 10; k++) se += expf(lg[k] - mx);
        float lse = mx + logf(se);
        #pragma unroll
        for (int k = 0; k < 10; k++) out[(size_t)b0 * 10 + k] = lg[k] - lse;

        if (a1) {
            mx = -1e30f;
            #pragma unroll
            for (int k = 0; k < 10; k++) {
                lg[k] = sB[k] + fcb[k];
                mx = fmaxf(mx, lg[k]);
            }
            se = 0.f;
            #pragma unroll
            for (int k = 0; k < 10; k++) se += expf(lg[k] - mx);
            lse = mx + logf(se);
            #pragma unroll
            for (int k = 0; k < 10; k++)
                out[(size_t)(b0 + 1) * 10 + k] = lg[k] - lse;
        }
    }
}

extern "C" void kernel_launch(void* const* d_in, const int* in_sizes, int n_in,
                              void* d_out, int out_size)
{
    const float* x   = (const float*)d_in[0];
    const float* qw  = (const float*)d_in[1];
    const float* w1  = (const float*)d_in[2];
    const float* g1  = (const float*)d_in[3];
    const float* be1 = (const float*)d_in[4];
    const float* w2  = (const float*)d_in[5];
    const float* g2  = (const float*)d_in[6];
    const float* be2 = (const float*)d_in[7];
    const float* fcw = (const float*)d_in[8];
    const float* fcb = (const float*)d_in[9];
    float* out = (float*)d_out;

    int B = in_sizes[0] / E;
    if (B > MAXB) B = MAXB;

    k_quanv_conv1<<<(B + 1) / 2, 128>>>(x, qw, w1, B);
    k_conv2<<<(B + 1) / 2, 128>>>(w2, g1, be1, B);
    k_fc<<<(B + 7) / 8, 128>>>(g2, be2, fcw, fcb, out, B);
}